// round 1
// baseline (speedup 1.0000x reference)
#include <cuda_runtime.h>
#include <math.h>

// Problem dims
#define BB 256
#define TT 128
#define II 256
#define HH 1024
#define CC 1000

// Scratch (static __device__ globals — allocation-free per harness rules)
// g_xp  : pre-activations  xp[b][t][h]   (reused by layer0 then layer1)
// g_hist: hidden history    h[b][t][h]   (layer0 output, then layer1 history)
__device__ float g_xp[(size_t)BB * TT * HH];     // 134 MB
__device__ float g_hist[(size_t)BB * TT * HH];   // 134 MB

// ---------------------------------------------------------------------------
// Projection GEMM: g_xp[m][n] = sum_k A[m][k] * W[n][k] + b1[n] + b2[n]
// M = B*T = 32768, N = H = 1024, K = II or HH. All tile-divisible.
// Tiles 64x64, BK=16, 256 threads, 4x4 per thread.
// useHist: A = g_hist (layer-1 projection) instead of the param pointer.
// ---------------------------------------------------------------------------
#define PBM 64
#define PBN 64
#define PBK 16

__global__ void proj_kernel(const float* __restrict__ Aparam,
                            const float* __restrict__ Wt,
                            const float* __restrict__ b1,
                            const float* __restrict__ b2,
                            int K, int useHist)
{
    const float* A = useHist ? g_hist : Aparam;

    const int bm = blockIdx.y;     // 0..511
    const int bn = blockIdx.x;     // 0..15

    __shared__ float As[PBK][PBM + 1];
    __shared__ float Bs[PBK][PBN + 1];

    const int tid = threadIdx.x;   // 0..255
    const int tx = tid & 15;       // k within BK on load; N-subtile on compute
    const int ty = tid >> 4;       // row group

    float acc[4][4];
    #pragma unroll
    for (int i = 0; i < 4; i++)
        #pragma unroll
        for (int j = 0; j < 4; j++) acc[i][j] = 0.f;

    const float* Ab = A  + (size_t)(bm * PBM) * K;
    const float* Wb = Wt + (size_t)(bn * PBN) * K;

    for (int k0 = 0; k0 < K; k0 += PBK) {
        #pragma unroll
        for (int p = 0; p < 4; p++) {
            int row = ty + p * 16;
            As[tx][row] = Ab[(size_t)row * K + k0 + tx];
            Bs[tx][row] = Wb[(size_t)row * K + k0 + tx];
        }
        __syncthreads();
        #pragma unroll
        for (int kk = 0; kk < PBK; kk++) {
            float a[4], w[4];
            #pragma unroll
            for (int i = 0; i < 4; i++) a[i] = As[kk][ty * 4 + i];
            #pragma unroll
            for (int j = 0; j < 4; j++) w[j] = Bs[kk][tx * 4 + j];
            #pragma unroll
            for (int i = 0; i < 4; i++)
                #pragma unroll
                for (int j = 0; j < 4; j++) acc[i][j] += a[i] * w[j];
        }
        __syncthreads();
    }

    #pragma unroll
    for (int i = 0; i < 4; i++) {
        int m = bm * PBM + ty * 4 + i;
        #pragma unroll
        for (int j = 0; j < 4; j++) {
            int n = bn * PBN + tx * 4 + j;
            g_xp[(size_t)m * HH + n] = acc[i][j] + b1[n] + b2[n];
        }
    }
}

// ---------------------------------------------------------------------------
// Recurrent step: for fixed t,
//   h[b][t][n] = tanh( xp[b][t][n] + sum_k h[b][t-1][k] * Whh[n][k] )
// M = B = 256 (tiles of 32), N = H = 1024 (tiles of 64), K = H.
// 256 threads, 2x4 outputs per thread. grid = (16, 8) = 128 CTAs.
// ---------------------------------------------------------------------------
#define SBM 32
#define SBN 64
#define SBK 16

__global__ void step_kernel(const float* __restrict__ Whh, int t)
{
    const int bm = blockIdx.y;     // 0..7  (batch tile)
    const int bn = blockIdx.x;     // 0..15 (hidden tile)

    __shared__ float As[SBK][SBM + 1];
    __shared__ float Bs[SBK][SBN + 1];

    const int tid = threadIdx.x;
    const int tx = tid & 15;
    const int ty = tid >> 4;

    float acc[2][4];
    #pragma unroll
    for (int i = 0; i < 2; i++)
        #pragma unroll
        for (int j = 0; j < 4; j++) acc[i][j] = 0.f;

    if (t > 0) {
        const float* hb = g_hist + (size_t)(t - 1) * HH;         // + b*T*H per row
        const float* Wb = Whh + (size_t)(bn * SBN) * HH;

        for (int k0 = 0; k0 < HH; k0 += SBK) {
            #pragma unroll
            for (int p = 0; p < 2; p++) {
                int row = ty + p * 16;
                int b   = bm * SBM + row;
                As[tx][row] = hb[(size_t)b * TT * HH + k0 + tx];
            }
            #pragma unroll
            for (int p = 0; p < 4; p++) {
                int row = ty + p * 16;
                Bs[tx][row] = Wb[(size_t)row * HH + k0 + tx];
            }
            __syncthreads();
            #pragma unroll
            for (int kk = 0; kk < SBK; kk++) {
                float a[2], w[4];
                a[0] = As[kk][ty * 2 + 0];
                a[1] = As[kk][ty * 2 + 1];
                #pragma unroll
                for (int j = 0; j < 4; j++) w[j] = Bs[kk][tx * 4 + j];
                #pragma unroll
                for (int i = 0; i < 2; i++)
                    #pragma unroll
                    for (int j = 0; j < 4; j++) acc[i][j] += a[i] * w[j];
            }
            __syncthreads();
        }
    }

    #pragma unroll
    for (int i = 0; i < 2; i++) {
        int b = bm * SBM + ty * 2 + i;
        size_t base = ((size_t)b * TT + t) * HH;
        #pragma unroll
        for (int j = 0; j < 4; j++) {
            int n = bn * SBN + tx * 4 + j;
            float v = tanhf(acc[i][j] + g_xp[base + n]);
            g_hist[base + n] = v;
        }
    }
}

// ---------------------------------------------------------------------------
// FC: out[b][c] = sum_k h[b][T-1][k] * fcW[c][k] + fcb[c]
// ---------------------------------------------------------------------------
__global__ void fc_kernel(const float* __restrict__ fcW,
                          const float* __restrict__ fcb,
                          float* __restrict__ out)
{
    int c = blockIdx.x * blockDim.x + threadIdx.x;
    int b = blockIdx.y;
    if (c >= CC) return;

    const float4* hv = (const float4*)(g_hist + ((size_t)b * TT + (TT - 1)) * HH);
    const float4* wv = (const float4*)(fcW + (size_t)c * HH);
    float acc = 0.f;
    #pragma unroll 4
    for (int k = 0; k < HH / 4; k++) {
        float4 h4 = hv[k];
        float4 w4 = wv[k];
        acc += h4.x * w4.x + h4.y * w4.y + h4.z * w4.z + h4.w * w4.w;
    }
    out[(size_t)b * CC + c] = acc + fcb[c];
}

// ---------------------------------------------------------------------------
extern "C" void kernel_launch(void* const* d_in, const int* in_sizes, int n_in,
                              void* d_out, int out_size)
{
    const float* x    = (const float*)d_in[0];
    const float* Wih0 = (const float*)d_in[1];
    const float* Whh0 = (const float*)d_in[2];
    const float* bih0 = (const float*)d_in[3];
    const float* bhh0 = (const float*)d_in[4];
    const float* Wih1 = (const float*)d_in[5];
    const float* Whh1 = (const float*)d_in[6];
    const float* bih1 = (const float*)d_in[7];
    const float* bhh1 = (const float*)d_in[8];
    const float* fcW  = (const float*)d_in[9];
    const float* fcb  = (const float*)d_in[10];
    float* out = (float*)d_out;

    const dim3 projGrid(HH / PBN, (BB * TT) / PBM);   // (16, 512)
    const dim3 stepGrid(HH / SBN, BB / SBM);          // (16, 8)

    // Layer 0
    proj_kernel<<<projGrid, 256>>>(x, Wih0, bih0, bhh0, II, 0);
    for (int t = 0; t < TT; t++)
        step_kernel<<<stepGrid, 256>>>(Whh0, t);

    // Layer 1 (input projection reads g_hist = layer-0 outputs)
    proj_kernel<<<projGrid, 256>>>(nullptr, Wih1, bih1, bhh1, HH, 1);
    for (int t = 0; t < TT; t++)
        step_kernel<<<stepGrid, 256>>>(Whh1, t);

    // Final FC on h2[:, T-1, :]
    fc_kernel<<<dim3((CC + 127) / 128, BB), 128>>>(fcW, fcb, out);
}

// round 5
// speedup vs baseline: 2.9439x; 2.9439x over previous
#include <cuda_runtime.h>
#include <cuda_bf16.h>
#include <math.h>
#include <stdint.h>

#define BB 256
#define TT 128
#define II 256
#define HH 1024
#define CC 1000

typedef __nv_bfloat16 bf16;

// ---------------- device scratch (allocation-free) ----------------
__device__ float g_xp[(size_t)BB * TT * HH];
__device__ bf16 g_xhi[(size_t)BB * TT * II];
__device__ bf16 g_xlo[(size_t)BB * TT * II];
__device__ bf16 g_h1hi[(size_t)BB * TT * HH];
__device__ bf16 g_h1lo[(size_t)BB * TT * HH];
__device__ bf16 g_h2hi[(size_t)BB * TT * HH];
__device__ bf16 g_h2lo[(size_t)BB * TT * HH];
__device__ bf16 g_Wih0hi[HH * II];  __device__ bf16 g_Wih0lo[HH * II];
__device__ bf16 g_Whh0hi[HH * HH];  __device__ bf16 g_Whh0lo[HH * HH];
__device__ bf16 g_Wih1hi[HH * HH];  __device__ bf16 g_Wih1lo[HH * HH];
__device__ bf16 g_Whh1hi[HH * HH];  __device__ bf16 g_Whh1lo[HH * HH];
__device__ bf16 g_fcWhi[HH * HH];   __device__ bf16 g_fcWlo[HH * HH];   // padded to 1024 rows

// ---------------- helpers ----------------
__device__ __forceinline__ uint32_t smem_u32(const void* p) {
    uint32_t a;
    asm("{ .reg .u64 t; cvta.to.shared.u64 t, %1; cvt.u32.u64 %0, t; }" : "=r"(a) : "l"(p));
    return a;
}
__device__ __forceinline__ void cp16(uint32_t dst, const void* src) {
    asm volatile("cp.async.cg.shared.global [%0], [%1], 16;" :: "r"(dst), "l"(src) : "memory");
}
#define CP_COMMIT() asm volatile("cp.async.commit_group;" ::: "memory")
#define CP_WAIT1()  asm volatile("cp.async.wait_group 1;" ::: "memory")
#define CP_WAIT0()  asm volatile("cp.async.wait_group 0;" ::: "memory")

__device__ __forceinline__ void mma16816(float* c, const uint32_t* a, const uint32_t* b) {
    asm volatile(
        "mma.sync.aligned.m16n8k16.row.col.f32.bf16.bf16.f32 "
        "{%0,%1,%2,%3}, {%4,%5,%6,%7}, {%8,%9}, {%0,%1,%2,%3};"
        : "+f"(c[0]), "+f"(c[1]), "+f"(c[2]), "+f"(c[3])
        : "r"(a[0]), "r"(a[1]), "r"(a[2]), "r"(a[3]), "r"(b[0]), "r"(b[1]));
}

__device__ __forceinline__ float fast_tanh(float x) {
    float e = __expf(2.f * x);
    return 1.f - __fdividef(2.f, e + 1.f);
}

// ---------------- split / small kernels ----------------
__global__ void split_kernel(const float* __restrict__ s, bf16* __restrict__ hi,
                             bf16* __restrict__ lo, int n) {
    int i = blockIdx.x * blockDim.x + threadIdx.x;
    if (i >= n) return;
    float v = s[i];
    bf16 h = __float2bfloat16(v);
    hi[i] = h;
    lo[i] = __float2bfloat16(v - __bfloat162float(h));
}

__global__ void split_pad_fc(const float* __restrict__ s, bf16* __restrict__ hi,
                             bf16* __restrict__ lo) {
    int i = blockIdx.x * blockDim.x + threadIdx.x;
    if (i >= HH * HH) return;
    int r = i >> 10, c = i & 1023;
    float v = (r < CC) ? s[r * HH + c] : 0.f;
    bf16 h = __float2bfloat16(v);
    hi[i] = h;
    lo[i] = __float2bfloat16(v - __bfloat162float(h));
}

__global__ void tanh0_kernel(bf16* __restrict__ ohi, bf16* __restrict__ olo) {
    int i = blockIdx.x * blockDim.x + threadIdx.x;
    if (i >= BB * HH) return;
    int b = i >> 10, n = i & 1023;
    size_t off = ((size_t)b * TT) * HH + n;
    float v = fast_tanh(g_xp[off]);
    bf16 h = __float2bfloat16(v);
    ohi[off] = h;
    olo[off] = __float2bfloat16(v - __bfloat162float(h));
}

// ---------------- split-bf16 tensor GEMM (mma.sync HMMA path) ----------------
// C[m][n] = (Ahi+Alo)(Whi+Wlo)^T to fp32 accuracy via 3 terms:
//           Ahi*Whi + Ahi*Wlo + Alo*Whi  (fp32 accumulate).
// CTA tile 32(M) x 64(N), 128 threads; warp tile 16x32; K chunks of 64, x3 terms.
// EPI 0: out fp32 = acc + e0[n] + e1[n]              (projection -> g_xp)
// EPI 1: v = tanh(acc + xp[m][n]); write hi/lo bf16  (recurrent step)
// EPI 2: out fp32 = acc + e0[n], guard n < CC        (final FC)
#define PAD_STRIDE 72   // bf16 elements per smem row (64 + 8 pad): conflict-free

template <int EPI>
__global__ void __launch_bounds__(128) gemm_kernel(
    const bf16* __restrict__ Ahi, const bf16* __restrict__ Alo,
    size_t rowA0, size_t strideA, int K,
    const bf16* __restrict__ Bhi, const bf16* __restrict__ Blo,
    const float* __restrict__ e0, const float* __restrict__ e1,
    size_t rowX0, size_t strideX,
    float* __restrict__ outF, size_t rowO0, size_t strideO,
    bf16* __restrict__ outHi, bf16* __restrict__ outLo)
{
    __shared__ __align__(16) bf16 sA[2][32 * PAD_STRIDE];
    __shared__ __align__(16) bf16 sB[2][64 * PAD_STRIDE];

    const int tid = threadIdx.x;
    const int bn = blockIdx.x, bm = blockIdx.y;
    const int wid = tid >> 5, lane = tid & 31;
    const int g = lane >> 2, tg = lane & 3;
    const int wm = wid & 1;        // 0..1  (16-row slice)
    const int wn = wid >> 1;       // 0..1  (32-col slice)

    const uint32_t sAu = smem_u32(sA);
    const uint32_t sBu = smem_u32(sB);

    float acc[4][4];               // [nt][reg]
    #pragma unroll
    for (int i = 0; i < 4; i++)
        #pragma unroll
        for (int j = 0; j < 4; j++) acc[i][j] = 0.f;

    const int CPT = K / 64;
    const int NC = 3 * CPT;

    auto load_chunk = [&](int c, int s) {
        int term = c / CPT;
        int kk = (c - term * CPT) * 64;
        const bf16* Ag = (term < 2) ? Ahi : Alo;
        const bf16* Wg = (term == 1) ? Blo : Bhi;
        uint32_t Ab = sAu + s * (32 * PAD_STRIDE * 2);
        uint32_t Bb = sBu + s * (64 * PAD_STRIDE * 2);
        #pragma unroll
        for (int i = 0; i < 2; i++) {                       // A: 32 rows x 8 segs = 256 tasks
            int task = tid + i * 128;
            int row = task >> 3, seg = task & 7;
            const bf16* src = Ag + rowA0 + (size_t)(bm * 32 + row) * strideA + kk + seg * 8;
            cp16(Ab + row * (PAD_STRIDE * 2) + seg * 16, src);
        }
        #pragma unroll
        for (int i = 0; i < 4; i++) {                       // B: 64 rows x 8 segs = 512 tasks
            int task = tid + i * 128;
            int row = task >> 3, seg = task & 7;
            const bf16* src = Wg + (size_t)(bn * 64 + row) * K + kk + seg * 8;
            cp16(Bb + row * (PAD_STRIDE * 2) + seg * 16, src);
        }
        CP_COMMIT();
    };

    load_chunk(0, 0);
    for (int c = 0; c < NC; c++) {
        int s = c & 1;
        if (c + 1 < NC) { load_chunk(c + 1, s ^ 1); CP_WAIT1(); }
        else             { CP_WAIT0(); }
        __syncthreads();

        const char* Ab = (const char*)sA + s * (32 * PAD_STRIDE * 2);
        const char* Bb = (const char*)sB + s * (64 * PAD_STRIDE * 2);

        #pragma unroll
        for (int k16 = 0; k16 < 4; k16++) {
            // A fragment: rows wm*16+g / +8, cols k16*16 + tg*2 (+8)
            uint32_t a[4];
            {
                const char* base = Ab + (wm * 16 + g) * (PAD_STRIDE * 2) + k16 * 32 + tg * 4;
                a[0] = *(const uint32_t*)(base);
                a[1] = *(const uint32_t*)(base + 8 * (PAD_STRIDE * 2));
                a[2] = *(const uint32_t*)(base + 16);
                a[3] = *(const uint32_t*)(base + 8 * (PAD_STRIDE * 2) + 16);
            }
            #pragma unroll
            for (int nt = 0; nt < 4; nt++) {
                uint32_t b[2];
                const char* base = Bb + (wn * 32 + nt * 8 + g) * (PAD_STRIDE * 2) + k16 * 32 + tg * 4;
                b[0] = *(const uint32_t*)(base);
                b[1] = *(const uint32_t*)(base + 16);
                mma16816(acc[nt], a, b);
            }
        }
        __syncthreads();
    }

    // ---------------- epilogue ----------------
    const int r0 = bm * 32 + wm * 16 + g;     // first output row
    #pragma unroll
    for (int nt = 0; nt < 4; nt++) {
        int n = bn * 64 + wn * 32 + nt * 8 + tg * 2;
        if (EPI == 0) {
            float b0 = e0[n] + e1[n], b1 = e0[n + 1] + e1[n + 1];
            float* p0 = outF + rowO0 + (size_t)r0 * strideO + n;
            float* p1 = outF + rowO0 + (size_t)(r0 + 8) * strideO + n;
            ((float2*)p0)[0] = make_float2(acc[nt][0] + b0, acc[nt][1] + b1);
            ((float2*)p1)[0] = make_float2(acc[nt][2] + b0, acc[nt][3] + b1);
        } else if (EPI == 1) {
            #pragma unroll
            for (int h = 0; h < 2; h++) {
                int r = r0 + h * 8;
                const float2 xp2 = *(const float2*)(e0 + rowX0 + (size_t)r * strideX + n);
                float v0 = fast_tanh(acc[nt][h * 2 + 0] + xp2.x);
                float v1 = fast_tanh(acc[nt][h * 2 + 1] + xp2.y);
                bf16 h0 = __float2bfloat16(v0);
                bf16 h1 = __float2bfloat16(v1);
                __nv_bfloat162 hp, lp;
                hp.x = h0; hp.y = h1;
                lp.x = __float2bfloat16(v0 - __bfloat162float(h0));
                lp.y = __float2bfloat16(v1 - __bfloat162float(h1));
                size_t go = rowO0 + (size_t)r * strideO + n;
                *(__nv_bfloat162*)(outHi + go) = hp;
                *(__nv_bfloat162*)(outLo + go) = lp;
            }
        } else {
            if (n < CC) {
                float b0 = e0[n], b1 = e0[n + 1];
                float* p0 = outF + rowO0 + (size_t)r0 * strideO + n;
                float* p1 = outF + rowO0 + (size_t)(r0 + 8) * strideO + n;
                ((float2*)p0)[0] = make_float2(acc[nt][0] + b0, acc[nt][1] + b1);
                ((float2*)p1)[0] = make_float2(acc[nt][2] + b0, acc[nt][3] + b1);
            }
        }
    }
}

// ---------------- host ----------------
extern "C" void kernel_launch(void* const* d_in, const int* in_sizes, int n_in,
                              void* d_out, int out_size)
{
    const float* x    = (const float*)d_in[0];
    const float* Wih0 = (const float*)d_in[1];
    const float* Whh0 = (const float*)d_in[2];
    const float* bih0 = (const float*)d_in[3];
    const float* bhh0 = (const float*)d_in[4];
    const float* Wih1 = (const float*)d_in[5];
    const float* Whh1 = (const float*)d_in[6];
    const float* bih1 = (const float*)d_in[7];
    const float* bhh1 = (const float*)d_in[8];
    const float* fcW  = (const float*)d_in[9];
    const float* fcb  = (const float*)d_in[10];
    float* out = (float*)d_out;

    void *p_xp, *p_xhi, *p_xlo, *p_h1hi, *p_h1lo, *p_h2hi, *p_h2lo;
    void *p_i0h, *p_i0l, *p_r0h, *p_r0l, *p_i1h, *p_i1l, *p_r1h, *p_r1l, *p_fch, *p_fcl;
    cudaGetSymbolAddress(&p_xp, g_xp);
    cudaGetSymbolAddress(&p_xhi, g_xhi);   cudaGetSymbolAddress(&p_xlo, g_xlo);
    cudaGetSymbolAddress(&p_h1hi, g_h1hi); cudaGetSymbolAddress(&p_h1lo, g_h1lo);
    cudaGetSymbolAddress(&p_h2hi, g_h2hi); cudaGetSymbolAddress(&p_h2lo, g_h2lo);
    cudaGetSymbolAddress(&p_i0h, g_Wih0hi); cudaGetSymbolAddress(&p_i0l, g_Wih0lo);
    cudaGetSymbolAddress(&p_r0h, g_Whh0hi); cudaGetSymbolAddress(&p_r0l, g_Whh0lo);
    cudaGetSymbolAddress(&p_i1h, g_Wih1hi); cudaGetSymbolAddress(&p_i1l, g_Wih1lo);
    cudaGetSymbolAddress(&p_r1h, g_Whh1hi); cudaGetSymbolAddress(&p_r1l, g_Whh1lo);
    cudaGetSymbolAddress(&p_fch, g_fcWhi);  cudaGetSymbolAddress(&p_fcl, g_fcWlo);

    // 1. fp32 -> bf16 hi/lo splits
    split_kernel<<<(BB * TT * II + 255) / 256, 256>>>(x, (bf16*)p_xhi, (bf16*)p_xlo, BB * TT * II);
    split_kernel<<<(HH * II + 255) / 256, 256>>>(Wih0, (bf16*)p_i0h, (bf16*)p_i0l, HH * II);
    split_kernel<<<(HH * HH + 255) / 256, 256>>>(Whh0, (bf16*)p_r0h, (bf16*)p_r0l, HH * HH);
    split_kernel<<<(HH * HH + 255) / 256, 256>>>(Wih1, (bf16*)p_i1h, (bf16*)p_i1l, HH * HH);
    split_kernel<<<(HH * HH + 255) / 256, 256>>>(Whh1, (bf16*)p_r1h, (bf16*)p_r1l, HH * HH);
    split_pad_fc<<<(HH * HH + 255) / 256, 256>>>(fcW, (bf16*)p_fch, (bf16*)p_fcl);

    const size_t TH = (size_t)TT * HH;
    const dim3 projGrid(HH / 64, (BB * TT) / 32);   // (16, 1024)
    const dim3 stepGrid(HH / 64, BB / 32);          // (16, 8) = 128 CTAs

    // 2. layer0 input projection: xp = x @ Wih0^T + bih0 + bhh0
    gemm_kernel<0><<<projGrid, 128>>>(
        (bf16*)p_xhi, (bf16*)p_xlo, 0, II, II,
        (bf16*)p_i0h, (bf16*)p_i0l, bih0, bhh0, 0, 0,
        (float*)p_xp, 0, HH, nullptr, nullptr);

    // 3. layer0 recurrence
    tanh0_kernel<<<(BB * HH + 255) / 256, 256>>>((bf16*)p_h1hi, (bf16*)p_h1lo);
    for (int t = 1; t < TT; t++)
        gemm_kernel<1><<<stepGrid, 128>>>(
            (bf16*)p_h1hi, (bf16*)p_h1lo, (size_t)(t - 1) * HH, TH, HH,
            (bf16*)p_r0h, (bf16*)p_r0l, (float*)p_xp, nullptr, (size_t)t * HH, TH,
            nullptr, (size_t)t * HH, TH, (bf16*)p_h1hi, (bf16*)p_h1lo);

    // 4. layer1 input projection: xp = h1 @ Wih1^T + bih1 + bhh1
    gemm_kernel<0><<<projGrid, 128>>>(
        (bf16*)p_h1hi, (bf16*)p_h1lo, 0, HH, HH,
        (bf16*)p_i1h, (bf16*)p_i1l, bih1, bhh1, 0, 0,
        (float*)p_xp, 0, HH, nullptr, nullptr);

    // 5. layer1 recurrence
    tanh0_kernel<<<(BB * HH + 255) / 256, 256>>>((bf16*)p_h2hi, (bf16*)p_h2lo);
    for (int t = 1; t < TT; t++)
        gemm_kernel<1><<<stepGrid, 128>>>(
            (bf16*)p_h2hi, (bf16*)p_h2lo, (size_t)(t - 1) * HH, TH, HH,
            (bf16*)p_r1h, (bf16*)p_r1l, (float*)p_xp, nullptr, (size_t)t * HH, TH,
            nullptr, (size_t)t * HH, TH, (bf16*)p_h2hi, (bf16*)p_h2lo);

    // 6. FC on h2[:, T-1, :]
    gemm_kernel<2><<<stepGrid, 128>>>(
        (bf16*)p_h2hi, (bf16*)p_h2lo, (size_t)(TT - 1) * HH, TH, HH,
        (bf16*)p_fch, (bf16*)p_fcl, fcb, nullptr, 0, 0,
        out, 0, CC, nullptr, nullptr);
}

// round 6
// speedup vs baseline: 4.2246x; 1.4350x over previous
#include <cuda_runtime.h>
#include <cuda_bf16.h>
#include <math.h>
#include <stdint.h>

#define BB 256
#define TT 128
#define II 256
#define HH 1024
#define CC 1000

typedef __nv_bfloat16 bf16;

// ---------------- device scratch (allocation-free) ----------------
__device__ float g_xp0[(size_t)BB * TT * HH];   // layer0 preactivations (bulk)
__device__ float g_xp1[(size_t)BB * TT * HH];   // layer1 preactivations (pipelined)
__device__ bf16 g_xhi[(size_t)BB * TT * II];
__device__ bf16 g_xlo[(size_t)BB * TT * II];
__device__ bf16 g_h1hi[(size_t)BB * TT * HH];
__device__ bf16 g_h1lo[(size_t)BB * TT * HH];
__device__ bf16 g_h2hi[(size_t)BB * TT * HH];
__device__ bf16 g_h2lo[(size_t)BB * TT * HH];
__device__ bf16 g_Wih0hi[HH * II];  __device__ bf16 g_Wih0lo[HH * II];
__device__ bf16 g_Whh0hi[HH * HH];  __device__ bf16 g_Whh0lo[HH * HH];
__device__ bf16 g_Wih1hi[HH * HH];  __device__ bf16 g_Wih1lo[HH * HH];
__device__ bf16 g_Whh1hi[HH * HH];  __device__ bf16 g_Whh1lo[HH * HH];
__device__ bf16 g_fcWhi[HH * HH];   __device__ bf16 g_fcWlo[HH * HH];   // padded to 1024 rows

// ---------------- helpers ----------------
__device__ __forceinline__ uint32_t smem_u32(const void* p) {
    uint32_t a;
    asm("{ .reg .u64 t; cvta.to.shared.u64 t, %1; cvt.u32.u64 %0, t; }" : "=r"(a) : "l"(p));
    return a;
}
__device__ __forceinline__ void cp16(uint32_t dst, const void* src) {
    asm volatile("cp.async.cg.shared.global [%0], [%1], 16;" :: "r"(dst), "l"(src) : "memory");
}
#define CP_COMMIT() asm volatile("cp.async.commit_group;" ::: "memory")
#define CP_WAIT1()  asm volatile("cp.async.wait_group 1;" ::: "memory")
#define CP_WAIT0()  asm volatile("cp.async.wait_group 0;" ::: "memory")

__device__ __forceinline__ void mma16816(float* c, const uint32_t* a, const uint32_t* b) {
    asm volatile(
        "mma.sync.aligned.m16n8k16.row.col.f32.bf16.bf16.f32 "
        "{%0,%1,%2,%3}, {%4,%5,%6,%7}, {%8,%9}, {%0,%1,%2,%3};"
        : "+f"(c[0]), "+f"(c[1]), "+f"(c[2]), "+f"(c[3])
        : "r"(a[0]), "r"(a[1]), "r"(a[2]), "r"(a[3]), "r"(b[0]), "r"(b[1]));
}

__device__ __forceinline__ float fast_tanh(float x) {
    float e = __expf(2.f * x);
    return 1.f - __fdividef(2.f, e + 1.f);
}

#define PAD_STRIDE 72   // bf16 elements per smem row (64 + 8 pad)

// ---------------- split kernels ----------------
__global__ void split_kernel(const float* __restrict__ s, bf16* __restrict__ hi,
                             bf16* __restrict__ lo, int n) {
    int i = blockIdx.x * blockDim.x + threadIdx.x;
    if (i >= n) return;
    float v = s[i];
    bf16 h = __float2bfloat16(v);
    hi[i] = h;
    lo[i] = __float2bfloat16(v - __bfloat162float(h));
}

__global__ void split_pad_fc(const float* __restrict__ s, bf16* __restrict__ hi,
                             bf16* __restrict__ lo) {
    int i = blockIdx.x * blockDim.x + threadIdx.x;
    if (i >= HH * HH) return;
    int r = i >> 10, c = i & 1023;
    float v = (r < CC) ? s[r * HH + c] : 0.f;
    bf16 h = __float2bfloat16(v);
    hi[i] = h;
    lo[i] = __float2bfloat16(v - __bfloat162float(h));
}

// ---------------- generic split-bf16 HMMA GEMM (bulk proj / FC) ----------------
// EPI 0: out fp32 = acc + e0[n] + e1[n]
// EPI 2: out fp32 = acc + e0[n], guard n < CC
template <int EPI>
__global__ void __launch_bounds__(128) gemm_kernel(
    const bf16* __restrict__ Ahi, const bf16* __restrict__ Alo,
    size_t rowA0, size_t strideA, int K,
    const bf16* __restrict__ Bhi, const bf16* __restrict__ Blo,
    const float* __restrict__ e0, const float* __restrict__ e1,
    float* __restrict__ outF, size_t rowO0, size_t strideO)
{
    __shared__ __align__(16) bf16 sA[2][32 * PAD_STRIDE];
    __shared__ __align__(16) bf16 sB[2][64 * PAD_STRIDE];

    const int tid = threadIdx.x;
    const int bn = blockIdx.x, bm = blockIdx.y;
    const int wid = tid >> 5, lane = tid & 31;
    const int g = lane >> 2, tg = lane & 3;
    const int wm = wid & 1, wn = wid >> 1;

    const uint32_t sAu = smem_u32(sA);
    const uint32_t sBu = smem_u32(sB);

    float acc[4][4];
    #pragma unroll
    for (int i = 0; i < 4; i++)
        #pragma unroll
        for (int j = 0; j < 4; j++) acc[i][j] = 0.f;

    const int CPT = K / 64;
    const int NC = 3 * CPT;

    auto load_chunk = [&](int c, int s) {
        int term = c / CPT;
        int kk = (c - term * CPT) * 64;
        const bf16* Ag = (term < 2) ? Ahi : Alo;
        const bf16* Wg = (term == 1) ? Blo : Bhi;
        uint32_t Ab = sAu + s * (32 * PAD_STRIDE * 2);
        uint32_t Bb = sBu + s * (64 * PAD_STRIDE * 2);
        #pragma unroll
        for (int i = 0; i < 2; i++) {
            int task = tid + i * 128;
            int row = task >> 3, seg = task & 7;
            const bf16* src = Ag + rowA0 + (size_t)(bm * 32 + row) * strideA + kk + seg * 8;
            cp16(Ab + row * (PAD_STRIDE * 2) + seg * 16, src);
        }
        #pragma unroll
        for (int i = 0; i < 4; i++) {
            int task = tid + i * 128;
            int row = task >> 3, seg = task & 7;
            const bf16* src = Wg + (size_t)(bn * 64 + row) * K + kk + seg * 8;
            cp16(Bb + row * (PAD_STRIDE * 2) + seg * 16, src);
        }
        CP_COMMIT();
    };

    load_chunk(0, 0);
    for (int c = 0; c < NC; c++) {
        int s = c & 1;
        if (c + 1 < NC) { load_chunk(c + 1, s ^ 1); CP_WAIT1(); }
        else             { CP_WAIT0(); }
        __syncthreads();
        const char* Ab = (const char*)sA + s * (32 * PAD_STRIDE * 2);
        const char* Bb = (const char*)sB + s * (64 * PAD_STRIDE * 2);
        #pragma unroll
        for (int k16 = 0; k16 < 4; k16++) {
            uint32_t a[4];
            {
                const char* base = Ab + (wm * 16 + g) * (PAD_STRIDE * 2) + k16 * 32 + tg * 4;
                a[0] = *(const uint32_t*)(base);
                a[1] = *(const uint32_t*)(base + 8 * (PAD_STRIDE * 2));
                a[2] = *(const uint32_t*)(base + 16);
                a[3] = *(const uint32_t*)(base + 8 * (PAD_STRIDE * 2) + 16);
            }
            #pragma unroll
            for (int nt = 0; nt < 4; nt++) {
                uint32_t b[2];
                const char* base = Bb + (wn * 32 + nt * 8 + g) * (PAD_STRIDE * 2) + k16 * 32 + tg * 4;
                b[0] = *(const uint32_t*)(base);
                b[1] = *(const uint32_t*)(base + 16);
                mma16816(acc[nt], a, b);
            }
        }
        __syncthreads();
    }

    const int r0 = bm * 32 + wm * 16 + g;
    #pragma unroll
    for (int nt = 0; nt < 4; nt++) {
        int n = bn * 64 + wn * 32 + nt * 8 + tg * 2;
        if (EPI == 0) {
            float b0 = e0[n] + e1[n], b1 = e0[n + 1] + e1[n + 1];
            float* p0 = outF + rowO0 + (size_t)r0 * strideO + n;
            float* p1 = outF + rowO0 + (size_t)(r0 + 8) * strideO + n;
            ((float2*)p0)[0] = make_float2(acc[nt][0] + b0, acc[nt][1] + b1);
            ((float2*)p1)[0] = make_float2(acc[nt][2] + b0, acc[nt][3] + b1);
        } else {
            if (n < CC) {
                float b0 = e0[n], b1 = e0[n + 1];
                float* p0 = outF + rowO0 + (size_t)r0 * strideO + n;
                float* p1 = outF + rowO0 + (size_t)(r0 + 8) * strideO + n;
                ((float2*)p0)[0] = make_float2(acc[nt][0] + b0, acc[nt][1] + b1);
                ((float2*)p1)[0] = make_float2(acc[nt][2] + b0, acc[nt][3] + b1);
            }
        }
    }
}

// ---------------- pipelined round kernel ----------------
// One launch per round r, grid (16, 8, 3). Phase z = blockIdx.z, t = r - z:
//  z=0: layer0 step:  h1[t] = tanh(xp0[t] + Whh0 @ h1[t-1])         (t in [0,127])
//  z=1: layer1 proj:  xp1[t] = Wih1 @ h1[t] + bih1 + bhh1           (t in [0,127])
//  z=2: layer1 step:  h2[t] = tanh(xp1[t] + Whh1 @ h2[t-1])         (t in [0,127])
// Cross-phase deps only on earlier rounds' outputs -> no intra-launch races.
__global__ void __launch_bounds__(128) round_kernel(
    int r,
    bf16* __restrict__ h1hi, bf16* __restrict__ h1lo,
    bf16* __restrict__ h2hi, bf16* __restrict__ h2lo,
    const bf16* __restrict__ Whh0hi, const bf16* __restrict__ Whh0lo,
    const bf16* __restrict__ Wih1hi, const bf16* __restrict__ Wih1lo,
    const bf16* __restrict__ Whh1hi, const bf16* __restrict__ Whh1lo,
    float* __restrict__ xp0, float* __restrict__ xp1,
    const float* __restrict__ bih1, const float* __restrict__ bhh1)
{
    const int z = blockIdx.z;
    const int t = r - z;
    if (t < 0 || t >= TT) return;

    // phase config
    const bf16 *Ahi, *Alo, *Whi, *Wlo;
    size_t rowA0 = 0;
    bool doGemm = true;
    const size_t TH = (size_t)TT * HH;

    if (z == 0) {
        Ahi = h1hi; Alo = h1lo; Whi = Whh0hi; Wlo = Whh0lo;
        rowA0 = (size_t)(t - 1) * HH;  doGemm = (t > 0);
    } else if (z == 1) {
        Ahi = h1hi; Alo = h1lo; Whi = Wih1hi; Wlo = Wih1lo;
        rowA0 = (size_t)t * HH;
    } else {
        Ahi = h2hi; Alo = h2lo; Whi = Whh1hi; Wlo = Whh1lo;
        rowA0 = (size_t)(t - 1) * HH;  doGemm = (t > 0);
    }

    __shared__ __align__(16) bf16 sA[2][32 * PAD_STRIDE];
    __shared__ __align__(16) bf16 sB[2][64 * PAD_STRIDE];

    const int tid = threadIdx.x;
    const int bn = blockIdx.x, bm = blockIdx.y;
    const int wid = tid >> 5, lane = tid & 31;
    const int g = lane >> 2, tg = lane & 3;
    const int wm = wid & 1, wn = wid >> 1;

    const uint32_t sAu = smem_u32(sA);
    const uint32_t sBu = smem_u32(sB);

    float acc[4][4];
    #pragma unroll
    for (int i = 0; i < 4; i++)
        #pragma unroll
        for (int j = 0; j < 4; j++) acc[i][j] = 0.f;

    const int CPT = 16;          // K = 1024
    const int NC = 48;

    if (doGemm) {
        auto load_chunk = [&](int c, int s) {
            int term = c / CPT;
            int kk = (c - term * CPT) * 64;
            const bf16* Ag = (term < 2) ? Ahi : Alo;
            const bf16* Wg = (term == 1) ? Wlo : Whi;
            uint32_t Ab = sAu + s * (32 * PAD_STRIDE * 2);
            uint32_t Bb = sBu + s * (64 * PAD_STRIDE * 2);
            #pragma unroll
            for (int i = 0; i < 2; i++) {
                int task = tid + i * 128;
                int row = task >> 3, seg = task & 7;
                const bf16* src = Ag + rowA0 + (size_t)(bm * 32 + row) * TH + kk + seg * 8;
                cp16(Ab + row * (PAD_STRIDE * 2) + seg * 16, src);
            }
            #pragma unroll
            for (int i = 0; i < 4; i++) {
                int task = tid + i * 128;
                int row = task >> 3, seg = task & 7;
                const bf16* src = Wg + (size_t)(bn * 64 + row) * HH + kk + seg * 8;
                cp16(Bb + row * (PAD_STRIDE * 2) + seg * 16, src);
            }
            CP_COMMIT();
        };

        load_chunk(0, 0);
        for (int c = 0; c < NC; c++) {
            int s = c & 1;
            if (c + 1 < NC) { load_chunk(c + 1, s ^ 1); CP_WAIT1(); }
            else             { CP_WAIT0(); }
            __syncthreads();
            const char* Ab = (const char*)sA + s * (32 * PAD_STRIDE * 2);
            const char* Bb = (const char*)sB + s * (64 * PAD_STRIDE * 2);
            #pragma unroll
            for (int k16 = 0; k16 < 4; k16++) {
                uint32_t a[4];
                {
                    const char* base = Ab + (wm * 16 + g) * (PAD_STRIDE * 2) + k16 * 32 + tg * 4;
                    a[0] = *(const uint32_t*)(base);
                    a[1] = *(const uint32_t*)(base + 8 * (PAD_STRIDE * 2));
                    a[2] = *(const uint32_t*)(base + 16);
                    a[3] = *(const uint32_t*)(base + 8 * (PAD_STRIDE * 2) + 16);
                }
                #pragma unroll
                for (int nt = 0; nt < 4; nt++) {
                    uint32_t b[2];
                    const char* base = Bb + (wn * 32 + nt * 8 + g) * (PAD_STRIDE * 2) + k16 * 32 + tg * 4;
                    b[0] = *(const uint32_t*)(base);
                    b[1] = *(const uint32_t*)(base + 16);
                    mma16816(acc[nt], a, b);
                }
            }
            __syncthreads();
        }
    }

    // ---------------- epilogue ----------------
    const int r0 = bm * 32 + wm * 16 + g;        // batch row
    const size_t rowT = (size_t)t * HH;

    #pragma unroll
    for (int nt = 0; nt < 4; nt++) {
        int n = bn * 64 + wn * 32 + nt * 8 + tg * 2;
        if (z == 1) {
            // proj epi: xp1 = acc + bih1 + bhh1
            float b0 = bih1[n] + bhh1[n], b1 = bih1[n + 1] + bhh1[n + 1];
            float* p0 = xp1 + rowT + (size_t)r0 * TH + n;
            float* p1 = xp1 + rowT + (size_t)(r0 + 8) * TH + n;
            ((float2*)p0)[0] = make_float2(acc[nt][0] + b0, acc[nt][1] + b1);
            ((float2*)p1)[0] = make_float2(acc[nt][2] + b0, acc[nt][3] + b1);
        } else {
            const float* xps = (z == 0) ? xp0 : xp1;
            bf16* oHi = (z == 0) ? h1hi : h2hi;
            bf16* oLo = (z == 0) ? h1lo : h2lo;
            #pragma unroll
            for (int h = 0; h < 2; h++) {
                int rr = r0 + h * 8;
                const float2 xp2 = *(const float2*)(xps + rowT + (size_t)rr * TH + n);
                float v0 = fast_tanh(acc[nt][h * 2 + 0] + xp2.x);
                float v1 = fast_tanh(acc[nt][h * 2 + 1] + xp2.y);
                bf16 h0 = __float2bfloat16(v0);
                bf16 h1v = __float2bfloat16(v1);
                __nv_bfloat162 hp, lp;
                hp.x = h0; hp.y = h1v;
                lp.x = __float2bfloat16(v0 - __bfloat162float(h0));
                lp.y = __float2bfloat16(v1 - __bfloat162float(h1v));
                size_t go = rowT + (size_t)rr * TH + n;
                *(__nv_bfloat162*)(oHi + go) = hp;
                *(__nv_bfloat162*)(oLo + go) = lp;
            }
        }
    }
}

// ---------------- host ----------------
extern "C" void kernel_launch(void* const* d_in, const int* in_sizes, int n_in,
                              void* d_out, int out_size)
{
    const float* x    = (const float*)d_in[0];
    const float* Wih0 = (const float*)d_in[1];
    const float* Whh0 = (const float*)d_in[2];
    const float* bih0 = (const float*)d_in[3];
    const float* bhh0 = (const float*)d_in[4];
    const float* Wih1 = (const float*)d_in[5];
    const float* Whh1 = (const float*)d_in[6];
    const float* bih1 = (const float*)d_in[7];
    const float* bhh1 = (const float*)d_in[8];
    const float* fcW  = (const float*)d_in[9];
    const float* fcb  = (const float*)d_in[10];
    float* out = (float*)d_out;

    void *p_xp0, *p_xp1, *p_xhi, *p_xlo, *p_h1hi, *p_h1lo, *p_h2hi, *p_h2lo;
    void *p_i0h, *p_i0l, *p_r0h, *p_r0l, *p_i1h, *p_i1l, *p_r1h, *p_r1l, *p_fch, *p_fcl;
    cudaGetSymbolAddress(&p_xp0, g_xp0);   cudaGetSymbolAddress(&p_xp1, g_xp1);
    cudaGetSymbolAddress(&p_xhi, g_xhi);   cudaGetSymbolAddress(&p_xlo, g_xlo);
    cudaGetSymbolAddress(&p_h1hi, g_h1hi); cudaGetSymbolAddress(&p_h1lo, g_h1lo);
    cudaGetSymbolAddress(&p_h2hi, g_h2hi); cudaGetSymbolAddress(&p_h2lo, g_h2lo);
    cudaGetSymbolAddress(&p_i0h, g_Wih0hi); cudaGetSymbolAddress(&p_i0l, g_Wih0lo);
    cudaGetSymbolAddress(&p_r0h, g_Whh0hi); cudaGetSymbolAddress(&p_r0l, g_Whh0lo);
    cudaGetSymbolAddress(&p_i1h, g_Wih1hi); cudaGetSymbolAddress(&p_i1l, g_Wih1lo);
    cudaGetSymbolAddress(&p_r1h, g_Whh1hi); cudaGetSymbolAddress(&p_r1l, g_Whh1lo);
    cudaGetSymbolAddress(&p_fch, g_fcWhi);  cudaGetSymbolAddress(&p_fcl, g_fcWlo);

    // 1. fp32 -> bf16 hi/lo splits
    split_kernel<<<(BB * TT * II + 255) / 256, 256>>>(x, (bf16*)p_xhi, (bf16*)p_xlo, BB * TT * II);
    split_kernel<<<(HH * II + 255) / 256, 256>>>(Wih0, (bf16*)p_i0h, (bf16*)p_i0l, HH * II);
    split_kernel<<<(HH * HH + 255) / 256, 256>>>(Whh0, (bf16*)p_r0h, (bf16*)p_r0l, HH * HH);
    split_kernel<<<(HH * HH + 255) / 256, 256>>>(Wih1, (bf16*)p_i1h, (bf16*)p_i1l, HH * HH);
    split_kernel<<<(HH * HH + 255) / 256, 256>>>(Whh1, (bf16*)p_r1h, (bf16*)p_r1l, HH * HH);
    split_pad_fc<<<(HH * HH + 255) / 256, 256>>>(fcW, (bf16*)p_fch, (bf16*)p_fcl);

    const size_t TH = (size_t)TT * HH;
    const dim3 projGrid(HH / 64, (BB * TT) / 32);   // (16, 1024)
    const dim3 roundGrid(HH / 64, BB / 32, 3);      // (16, 8, 3) = 384 CTAs
    const dim3 fcGrid(HH / 64, BB / 32);            // (16, 8)

    // 2. layer0 bulk input projection: xp0 = x @ Wih0^T + bih0 + bhh0
    gemm_kernel<0><<<projGrid, 128>>>(
        (bf16*)p_xhi, (bf16*)p_xlo, 0, II, II,
        (bf16*)p_i0h, (bf16*)p_i0l, bih0, bhh0,
        (float*)p_xp0, 0, HH);

    // 3. pipelined rounds: layer0 step | layer1 proj | layer1 step
    for (int r = 0; r <= TT + 1; r++)
        round_kernel<<<roundGrid, 128>>>(
            r,
            (bf16*)p_h1hi, (bf16*)p_h1lo, (bf16*)p_h2hi, (bf16*)p_h2lo,
            (bf16*)p_r0h, (bf16*)p_r0l,
            (bf16*)p_i1h, (bf16*)p_i1l,
            (bf16*)p_r1h, (bf16*)p_r1l,
            (float*)p_xp0, (float*)p_xp1, bih1, bhh1);

    // 4. FC on h2[:, T-1, :]
    gemm_kernel<2><<<fcGrid, 128>>>(
        (bf16*)p_h2hi, (bf16*)p_h2lo, (size_t)(TT - 1) * HH, TH, HH,
        (bf16*)p_fch, (bf16*)p_fcl, fcb, nullptr,
        out, 0, CC);
}

// round 7
// speedup vs baseline: 4.2836x; 1.0140x over previous
#include <cuda_runtime.h>
#include <cuda_bf16.h>
#include <math.h>
#include <stdint.h>

#define BB 256
#define TT 128
#define II 256
#define HH 1024
#define CC 1000

typedef __nv_bfloat16 bf16;

// ---------------- device scratch (allocation-free) ----------------
__device__ float g_xp0[(size_t)BB * TT * HH];   // layer0 preactivations (bulk)
__device__ float g_xp1[(size_t)BB * TT * HH];   // layer1 preactivations (pipelined)
__device__ bf16 g_xhi[(size_t)BB * TT * II];
__device__ bf16 g_xlo[(size_t)BB * TT * II];
__device__ bf16 g_h1hi[(size_t)BB * TT * HH];
__device__ bf16 g_h1lo[(size_t)BB * TT * HH];
__device__ bf16 g_h2hi[(size_t)BB * TT * HH];
__device__ bf16 g_h2lo[(size_t)BB * TT * HH];
__device__ bf16 g_Wih0hi[HH * II];  __device__ bf16 g_Wih0lo[HH * II];
__device__ bf16 g_Whh0hi[HH * HH];  __device__ bf16 g_Whh0lo[HH * HH];
__device__ bf16 g_Wih1hi[HH * HH];  __device__ bf16 g_Wih1lo[HH * HH];
__device__ bf16 g_Whh1hi[HH * HH];  __device__ bf16 g_Whh1lo[HH * HH];
__device__ bf16 g_fcWhi[HH * HH];   __device__ bf16 g_fcWlo[HH * HH];   // padded to 1024 rows

// ---------------- helpers ----------------
__device__ __forceinline__ uint32_t smem_u32(const void* p) {
    uint32_t a;
    asm("{ .reg .u64 t; cvta.to.shared.u64 t, %1; cvt.u32.u64 %0, t; }" : "=r"(a) : "l"(p));
    return a;
}
__device__ __forceinline__ void cp16(uint32_t dst, const void* src) {
    asm volatile("cp.async.cg.shared.global [%0], [%1], 16;" :: "r"(dst), "l"(src) : "memory");
}
#define CP_COMMIT() asm volatile("cp.async.commit_group;" ::: "memory")
#define CP_WAITG(n) asm volatile("cp.async.wait_group %0;" :: "n"(n) : "memory")

__device__ __forceinline__ void ldsm4(uint32_t* r, uint32_t addr) {
    asm volatile("ldmatrix.sync.aligned.m8n8.x4.shared.b16 {%0,%1,%2,%3}, [%4];"
        : "=r"(r[0]), "=r"(r[1]), "=r"(r[2]), "=r"(r[3]) : "r"(addr));
}

__device__ __forceinline__ void mma16816(float* c, const uint32_t* a, const uint32_t* b) {
    asm volatile(
        "mma.sync.aligned.m16n8k16.row.col.f32.bf16.bf16.f32 "
        "{%0,%1,%2,%3}, {%4,%5,%6,%7}, {%8,%9}, {%0,%1,%2,%3};"
        : "+f"(c[0]), "+f"(c[1]), "+f"(c[2]), "+f"(c[3])
        : "r"(a[0]), "r"(a[1]), "r"(a[2]), "r"(a[3]), "r"(b[0]), "r"(b[1]));
}

__device__ __forceinline__ float fast_tanh(float x) {
    float e = __expf(2.f * x);
    return 1.f - __fdividef(2.f, e + 1.f);
}

#define PAD_STRIDE 72                      // bf16 per smem row (64 + 8 pad) = 144 B
#define ROWB (PAD_STRIDE * 2)

// ---------------- split kernels ----------------
__global__ void split_kernel(const float* __restrict__ s, bf16* __restrict__ hi,
                             bf16* __restrict__ lo, int n) {
    int i = blockIdx.x * blockDim.x + threadIdx.x;
    if (i >= n) return;
    float v = s[i];
    bf16 h = __float2bfloat16(v);
    hi[i] = h;
    lo[i] = __float2bfloat16(v - __bfloat162float(h));
}

__global__ void split_pad_fc(const float* __restrict__ s, bf16* __restrict__ hi,
                             bf16* __restrict__ lo) {
    int i = blockIdx.x * blockDim.x + threadIdx.x;
    if (i >= HH * HH) return;
    int r = i >> 10, c = i & 1023;
    float v = (r < CC) ? s[r * HH + c] : 0.f;
    bf16 h = __float2bfloat16(v);
    hi[i] = h;
    lo[i] = __float2bfloat16(v - __bfloat162float(h));
}

// ---------------- shared mainloop (3-stage cp.async + ldmatrix) ----------------
// Computes acc += 3-term split product for a 32x64 CTA tile.
// sA/sB: 3-stage smem. A rows from (Ahi|Alo)+rowA0+row*strideA, W rows n*K.
struct MLArgs {
    const bf16 *Ahi, *Alo, *Whi, *Wlo;
    size_t rowA0, strideA;
    int K;          // K per term (multiple of 64)
};

__device__ __forceinline__ void run_mainloop(
    float acc[4][4], const MLArgs& ml,
    bf16* sA, bf16* sB,            // [3][32*PAD_STRIDE], [3][64*PAD_STRIDE]
    int tid, int bm, int bn)
{
    const int lane = tid & 31;
    const int wid = tid >> 5;
    const int wm = wid & 1, wn = wid >> 1;

    const uint32_t sAu = smem_u32(sA);
    const uint32_t sBu = smem_u32(sB);

    const int CPT = ml.K / 64;
    const int NC = 3 * CPT;

    auto load_chunk = [&](int c, int s) {
        int term = c / CPT;
        int kk = (c - term * CPT) * 64;
        const bf16* Ag = (term < 2) ? ml.Ahi : ml.Alo;
        const bf16* Wg = (term == 1) ? ml.Wlo : ml.Whi;
        uint32_t Ab = sAu + s * (32 * ROWB);
        uint32_t Bb = sBu + s * (64 * ROWB);
        #pragma unroll
        for (int i = 0; i < 2; i++) {               // A: 32 rows x 8 segs
            int task = tid + i * 128;
            int row = task >> 3, seg = task & 7;
            const bf16* src = Ag + ml.rowA0 + (size_t)(bm * 32 + row) * ml.strideA + kk + seg * 8;
            cp16(Ab + row * ROWB + seg * 16, src);
        }
        #pragma unroll
        for (int i = 0; i < 4; i++) {               // B: 64 rows x 8 segs
            int task = tid + i * 128;
            int row = task >> 3, seg = task & 7;
            const bf16* src = Wg + (size_t)(bn * 64 + row) * ml.K + kk + seg * 8;
            cp16(Bb + row * ROWB + seg * 16, src);
        }
        CP_COMMIT();
    };

    // ldmatrix lane addressing (stage-relative offsets)
    const uint32_t aOff = (uint32_t)(wm * 16 + (lane & 15)) * ROWB + ((lane >> 4) & 1) * 16;
    const uint32_t bRow = (uint32_t)(wn * 32 + ((lane >> 4) & 1) * 8 + (lane & 7));
    const uint32_t bOff = bRow * ROWB + ((lane >> 3) & 1) * 16;

    load_chunk(0, 0);
    load_chunk(1, 1);
    for (int c = 0; c < NC; c++) {
        int s = c - (c / 3) * 3;                    // c % 3
        CP_WAITG(1);                                // chunk c resident
        __syncthreads();
        uint32_t Ab = sAu + s * (32 * ROWB) + aOff;
        uint32_t Bb = sBu + s * (64 * ROWB) + bOff;
        #pragma unroll
        for (int k16 = 0; k16 < 4; k16++) {
            uint32_t a[4], b01[4], b23[4];
            ldsm4(a, Ab + k16 * 32);
            ldsm4(b01, Bb + k16 * 32);              // nt 0,1
            ldsm4(b23, Bb + 16 * ROWB + k16 * 32);  // nt 2,3
            mma16816(acc[0], a, b01);
            mma16816(acc[1], a, b01 + 2);
            mma16816(acc[2], a, b23);
            mma16816(acc[3], a, b23 + 2);
        }
        __syncthreads();
        if (c + 2 < NC) load_chunk(c + 2, (c + 2) - ((c + 2) / 3) * 3);
    }
}

// ---------------- generic split-bf16 HMMA GEMM (bulk proj / FC) ----------------
// EPI 0: out fp32 = acc + e0[n] + e1[n]
// EPI 2: out fp32 = acc + e0[n], guard n < CC
template <int EPI>
__global__ void __launch_bounds__(128) gemm_kernel(
    const bf16* __restrict__ Ahi, const bf16* __restrict__ Alo,
    size_t rowA0, size_t strideA, int K,
    const bf16* __restrict__ Bhi, const bf16* __restrict__ Blo,
    const float* __restrict__ e0, const float* __restrict__ e1,
    float* __restrict__ outF, size_t rowO0, size_t strideO)
{
    __shared__ __align__(16) bf16 sA[3][32 * PAD_STRIDE];
    __shared__ __align__(16) bf16 sB[3][64 * PAD_STRIDE];

    const int tid = threadIdx.x;
    const int bn = blockIdx.x, bm = blockIdx.y;
    const int wid = tid >> 5, lane = tid & 31;
    const int g = lane >> 2, tg = lane & 3;
    const int wm = wid & 1, wn = wid >> 1;

    float acc[4][4];
    #pragma unroll
    for (int i = 0; i < 4; i++)
        #pragma unroll
        for (int j = 0; j < 4; j++) acc[i][j] = 0.f;

    MLArgs ml{Ahi, Alo, Bhi, Blo, rowA0, strideA, K};
    run_mainloop(acc, ml, &sA[0][0], &sB[0][0], tid, bm, bn);

    const int r0 = bm * 32 + wm * 16 + g;
    #pragma unroll
    for (int nt = 0; nt < 4; nt++) {
        int n = bn * 64 + wn * 32 + nt * 8 + tg * 2;
        if (EPI == 0) {
            float b0 = e0[n] + e1[n], b1 = e0[n + 1] + e1[n + 1];
            float* p0 = outF + rowO0 + (size_t)r0 * strideO + n;
            float* p1 = outF + rowO0 + (size_t)(r0 + 8) * strideO + n;
            ((float2*)p0)[0] = make_float2(acc[nt][0] + b0, acc[nt][1] + b1);
            ((float2*)p1)[0] = make_float2(acc[nt][2] + b0, acc[nt][3] + b1);
        } else {
            if (n < CC) {
                float b0 = e0[n], b1 = e0[n + 1];
                float* p0 = outF + rowO0 + (size_t)r0 * strideO + n;
                float* p1 = outF + rowO0 + (size_t)(r0 + 8) * strideO + n;
                ((float2*)p0)[0] = make_float2(acc[nt][0] + b0, acc[nt][1] + b1);
                ((float2*)p1)[0] = make_float2(acc[nt][2] + b0, acc[nt][3] + b1);
            }
        }
    }
}

// ---------------- pipelined round kernel ----------------
// Phase z = blockIdx.z, t = r - z:
//  z=0: h1[t] = tanh(xp0[t] + Whh0 @ h1[t-1])
//  z=1: xp1[t] = Wih1 @ h1[t] + bih1 + bhh1
//  z=2: h2[t] = tanh(xp1[t] + Whh1 @ h2[t-1])
__global__ void __launch_bounds__(128) round_kernel(
    int r,
    bf16* __restrict__ h1hi, bf16* __restrict__ h1lo,
    bf16* __restrict__ h2hi, bf16* __restrict__ h2lo,
    const bf16* __restrict__ Whh0hi, const bf16* __restrict__ Whh0lo,
    const bf16* __restrict__ Wih1hi, const bf16* __restrict__ Wih1lo,
    const bf16* __restrict__ Whh1hi, const bf16* __restrict__ Whh1lo,
    float* __restrict__ xp0, float* __restrict__ xp1,
    const float* __restrict__ bih1, const float* __restrict__ bhh1)
{
    const int z = blockIdx.z;
    const int t = r - z;
    if (t < 0 || t >= TT) return;

    const size_t TH = (size_t)TT * HH;
    MLArgs ml;
    ml.strideA = TH;  ml.K = HH;
    bool doGemm = true;
    if (z == 0) {
        ml.Ahi = h1hi; ml.Alo = h1lo; ml.Whi = Whh0hi; ml.Wlo = Whh0lo;
        ml.rowA0 = (size_t)(t - 1) * HH;  doGemm = (t > 0);
    } else if (z == 1) {
        ml.Ahi = h1hi; ml.Alo = h1lo; ml.Whi = Wih1hi; ml.Wlo = Wih1lo;
        ml.rowA0 = (size_t)t * HH;
    } else {
        ml.Ahi = h2hi; ml.Alo = h2lo; ml.Whi = Whh1hi; ml.Wlo = Whh1lo;
        ml.rowA0 = (size_t)(t - 1) * HH;  doGemm = (t > 0);
    }

    __shared__ __align__(16) bf16 sA[3][32 * PAD_STRIDE];
    __shared__ __align__(16) bf16 sB[3][64 * PAD_STRIDE];

    const int tid = threadIdx.x;
    const int bn = blockIdx.x, bm = blockIdx.y;
    const int wid = tid >> 5, lane = tid & 31;
    const int g = lane >> 2, tg = lane & 3;
    const int wm = wid & 1, wn = wid >> 1;

    float acc[4][4];
    #pragma unroll
    for (int i = 0; i < 4; i++)
        #pragma unroll
        for (int j = 0; j < 4; j++) acc[i][j] = 0.f;

    if (doGemm)
        run_mainloop(acc, ml, &sA[0][0], &sB[0][0], tid, bm, bn);

    // ---------------- epilogue ----------------
    const int r0 = bm * 32 + wm * 16 + g;
    const size_t rowT = (size_t)t * HH;

    #pragma unroll
    for (int nt = 0; nt < 4; nt++) {
        int n = bn * 64 + wn * 32 + nt * 8 + tg * 2;
        if (z == 1) {
            float b0 = bih1[n] + bhh1[n], b1 = bih1[n + 1] + bhh1[n + 1];
            float* p0 = xp1 + rowT + (size_t)r0 * TH + n;
            float* p1 = xp1 + rowT + (size_t)(r0 + 8) * TH + n;
            ((float2*)p0)[0] = make_float2(acc[nt][0] + b0, acc[nt][1] + b1);
            ((float2*)p1)[0] = make_float2(acc[nt][2] + b0, acc[nt][3] + b1);
        } else {
            const float* xps = (z == 0) ? xp0 : xp1;
            bf16* oHi = (z == 0) ? h1hi : h2hi;
            bf16* oLo = (z == 0) ? h1lo : h2lo;
            #pragma unroll
            for (int h = 0; h < 2; h++) {
                int rr = r0 + h * 8;
                const float2 xp2 = *(const float2*)(xps + rowT + (size_t)rr * TH + n);
                float v0 = fast_tanh(acc[nt][h * 2 + 0] + xp2.x);
                float v1 = fast_tanh(acc[nt][h * 2 + 1] + xp2.y);
                bf16 h0 = __float2bfloat16(v0);
                bf16 h1v = __float2bfloat16(v1);
                __nv_bfloat162 hp, lp;
                hp.x = h0; hp.y = h1v;
                lp.x = __float2bfloat16(v0 - __bfloat162float(h0));
                lp.y = __float2bfloat16(v1 - __bfloat162float(h1v));
                size_t go = rowT + (size_t)rr * TH + n;
                *(__nv_bfloat162*)(oHi + go) = hp;
                *(__nv_bfloat162*)(oLo + go) = lp;
            }
        }
    }
}

// ---------------- host ----------------
extern "C" void kernel_launch(void* const* d_in, const int* in_sizes, int n_in,
                              void* d_out, int out_size)
{
    const float* x    = (const float*)d_in[0];
    const float* Wih0 = (const float*)d_in[1];
    const float* Whh0 = (const float*)d_in[2];
    const float* bih0 = (const float*)d_in[3];
    const float* bhh0 = (const float*)d_in[4];
    const float* Wih1 = (const float*)d_in[5];
    const float* Whh1 = (const float*)d_in[6];
    const float* bih1 = (const float*)d_in[7];
    const float* bhh1 = (const float*)d_in[8];
    const float* fcW  = (const float*)d_in[9];
    const float* fcb  = (const float*)d_in[10];
    float* out = (float*)d_out;

    void *p_xp0, *p_xp1, *p_xhi, *p_xlo, *p_h1hi, *p_h1lo, *p_h2hi, *p_h2lo;
    void *p_i0h, *p_i0l, *p_r0h, *p_r0l, *p_i1h, *p_i1l, *p_r1h, *p_r1l, *p_fch, *p_fcl;
    cudaGetSymbolAddress(&p_xp0, g_xp0);   cudaGetSymbolAddress(&p_xp1, g_xp1);
    cudaGetSymbolAddress(&p_xhi, g_xhi);   cudaGetSymbolAddress(&p_xlo, g_xlo);
    cudaGetSymbolAddress(&p_h1hi, g_h1hi); cudaGetSymbolAddress(&p_h1lo, g_h1lo);
    cudaGetSymbolAddress(&p_h2hi, g_h2hi); cudaGetSymbolAddress(&p_h2lo, g_h2lo);
    cudaGetSymbolAddress(&p_i0h, g_Wih0hi); cudaGetSymbolAddress(&p_i0l, g_Wih0lo);
    cudaGetSymbolAddress(&p_r0h, g_Whh0hi); cudaGetSymbolAddress(&p_r0l, g_Whh0lo);
    cudaGetSymbolAddress(&p_i1h, g_Wih1hi); cudaGetSymbolAddress(&p_i1l, g_Wih1lo);
    cudaGetSymbolAddress(&p_r1h, g_Whh1hi); cudaGetSymbolAddress(&p_r1l, g_Whh1lo);
    cudaGetSymbolAddress(&p_fch, g_fcWhi);  cudaGetSymbolAddress(&p_fcl, g_fcWlo);

    // 1. fp32 -> bf16 hi/lo splits
    split_kernel<<<(BB * TT * II + 255) / 256, 256>>>(x, (bf16*)p_xhi, (bf16*)p_xlo, BB * TT * II);
    split_kernel<<<(HH * II + 255) / 256, 256>>>(Wih0, (bf16*)p_i0h, (bf16*)p_i0l, HH * II);
    split_kernel<<<(HH * HH + 255) / 256, 256>>>(Whh0, (bf16*)p_r0h, (bf16*)p_r0l, HH * HH);
    split_kernel<<<(HH * HH + 255) / 256, 256>>>(Wih1, (bf16*)p_i1h, (bf16*)p_i1l, HH * HH);
    split_kernel<<<(HH * HH + 255) / 256, 256>>>(Whh1, (bf16*)p_r1h, (bf16*)p_r1l, HH * HH);
    split_pad_fc<<<(HH * HH + 255) / 256, 256>>>(fcW, (bf16*)p_fch, (bf16*)p_fcl);

    const size_t TH = (size_t)TT * HH;
    const dim3 projGrid(HH / 64, (BB * TT) / 32);   // (16, 1024)
    const dim3 roundGrid(HH / 64, BB / 32, 3);      // (16, 8, 3) = 384 CTAs
    const dim3 fcGrid(HH / 64, BB / 32);            // (16, 8)

    // 2. layer0 bulk input projection: xp0 = x @ Wih0^T + bih0 + bhh0
    gemm_kernel<0><<<projGrid, 128>>>(
        (bf16*)p_xhi, (bf16*)p_xlo, 0, II, II,
        (bf16*)p_i0h, (bf16*)p_i0l, bih0, bhh0,
        (float*)p_xp0, 0, HH);

    // 3. pipelined rounds: layer0 step | layer1 proj | layer1 step
    for (int r = 0; r <= TT + 1; r++)
        round_kernel<<<roundGrid, 128>>>(
            r,
            (bf16*)p_h1hi, (bf16*)p_h1lo, (bf16*)p_h2hi, (bf16*)p_h2lo,
            (bf16*)p_r0h, (bf16*)p_r0l,
            (bf16*)p_i1h, (bf16*)p_i1l,
            (bf16*)p_r1h, (bf16*)p_r1l,
            (float*)p_xp0, (float*)p_xp1, bih1, bhh1);

    // 4. FC on h2[:, T-1, :]
    gemm_kernel<2><<<fcGrid, 128>>>(
        (bf16*)p_h2hi, (bf16*)p_h2lo, (size_t)(TT - 1) * HH, TH, HH,
        (bf16*)p_fch, (bf16*)p_fcl, fcb, nullptr,
        out, 0, CC);
}